// round 4
// baseline (speedup 1.0000x reference)
#include <cuda_runtime.h>
#include <cstdint>

#define B_    4
#define KL    128
#define XL    4096
#define DIM   256
#define H_    8
#define HD    32
#define PB    8
#define NDIS  66
#define TDIM  768           // 3*DIM
#define SCALE 0.17677669529663687f
#define NMASK (B_ * H_ * XL * KL)

// ---------------- scratch (device globals: no allocs allowed) ----------------
__device__ float    g_QKVx[B_ * XL * TDIM];
__device__ float    g_QKVk[B_ * KL * TDIM];
__device__ float    g_S[(size_t)B_ * H_ * KL * XL];
__device__ float    g_oriP[8 * B_ * H_ * KL * PB];
__device__ int      g_mo[B_ * H_ * KL];
__device__ uint8_t  g_maskT[(size_t)NMASK];            // (b,h,k,x)
__device__ float    g_part[B_ * H_ * 8 * KL * 34];
__device__ float    g_preK[B_ * KL * DIM];
__device__ float    g_preX[B_ * XL * DIM];
__device__ unsigned g_flags;

// ---------------- mask dtype probe ----------------
__global__ void det_reset() { if (threadIdx.x == 0) g_flags = 0u; }

__global__ void det_scan(const unsigned* __restrict__ w)
{
    int i = blockIdx.x * blockDim.x + threadIdx.x;
    unsigned v = w[i];
    unsigned f = 0;
    if (v == 0x3F800000u) f |= 1u;                 // float 1.0 pattern
    else if (v != 0u && v != 1u) f |= 2u;          // impossible for int32 0/1
    for (int o = 16; o > 0; o >>= 1) f |= __shfl_xor_sync(0xffffffffu, f, o);
    if ((threadIdx.x & 31) == 0 && f) atomicOr(&g_flags, f);
}

// ---------------- fused mask canonicalize + transpose -> g_maskT ----------
// grid (XL/128, KL/32, B*H), block (32,8)
__global__ void conv_transpose_mask(const void* __restrict__ m)
{
    __shared__ uint8_t tile[32][132];   // [k][x], 132B row => conflict-free
    unsigned flags = g_flags;
    int mode = (flags & 1u) ? 2 : ((flags & 2u) ? 0 : 1);  // 0=u8 1=i32 2=f32
    int x0 = blockIdx.x * 128, k0 = blockIdx.y * 32, bh = blockIdx.z;
    int tx = threadIdx.x, ty = threadIdx.y;
    const size_t baseIn = ((size_t)bh * XL + x0) * KL + k0;
#pragma unroll 4
    for (int p = 0; p < 16; p++) {
        int xi = p * 8 + ty;
        uint8_t v;
        if (mode == 1)      v = ((const int*)m)[baseIn + (size_t)xi * KL + tx] != 0;
        else if (mode == 2) v = ((const float*)m)[baseIn + (size_t)xi * KL + tx] != 0.f;
        else                v = ((const uint8_t*)m)[baseIn + (size_t)xi * KL + tx] != 0;
        tile[tx][xi] = v;
    }
    __syncthreads();
#pragma unroll
    for (int p = 0; p < 4; p++) {
        int kr = p * 8 + ty;
        uchar4 o = make_uchar4(tile[kr][tx * 4 + 0], tile[kr][tx * 4 + 1],
                               tile[kr][tx * 4 + 2], tile[kr][tx * 4 + 3]);
        *(uchar4*)&g_maskT[((size_t)bh * KL + k0 + kr) * XL + x0 + tx * 4] = o;
    }
}

// ---------------- SGEMM: double-buffered, BK=16, 128x128 tile -------------
__global__ __launch_bounds__(256) void sgemm_db(
    const float* __restrict__ A, const float* __restrict__ Bm,
    const float* __restrict__ bias, float* __restrict__ C,
    int M, int N, int K)
{
    const int BK = 16;
    __shared__ float As[2][BK][132];    // transposed A tile, padded
    __shared__ float Bs[2][BK][128];
    int tid = threadIdx.x;
    int cRow = blockIdx.y, cCol = blockIdx.x;
    const float* Ap = A + (size_t)cRow * 128 * K;
    const float* Bp = Bm + cCol * 128;
    float* Cp = C + (size_t)cRow * 128 * N + cCol * 128;

    int rowA = tid >> 2, slotA = tid & 3;     // A: rows 0..63 (+64), 4 f4-slots
    int rowB = tid >> 5, colB = tid & 31;     // B: rows 0..7 (+8), 32 f4-cols
    int tr = tid >> 4, tc = tid & 15;

    float4 a0, a1, b0, b1;
    a0 = *(const float4*)&Ap[(size_t)rowA * K + slotA * 4];
    a1 = *(const float4*)&Ap[(size_t)(rowA + 64) * K + slotA * 4];
    b0 = *(const float4*)&Bp[(size_t)rowB * N + colB * 4];
    b1 = *(const float4*)&Bp[(size_t)(rowB + 8) * N + colB * 4];

    As[0][slotA * 4 + 0][rowA] = a0.x;  As[0][slotA * 4 + 1][rowA] = a0.y;
    As[0][slotA * 4 + 2][rowA] = a0.z;  As[0][slotA * 4 + 3][rowA] = a0.w;
    As[0][slotA * 4 + 0][rowA + 64] = a1.x;  As[0][slotA * 4 + 1][rowA + 64] = a1.y;
    As[0][slotA * 4 + 2][rowA + 64] = a1.z;  As[0][slotA * 4 + 3][rowA + 64] = a1.w;
    *(float4*)&Bs[0][rowB][colB * 4] = b0;
    *(float4*)&Bs[0][rowB + 8][colB * 4] = b1;
    __syncthreads();

    float acc[64];
#pragma unroll
    for (int i = 0; i < 64; i++) acc[i] = 0.f;

    int nIter = K / BK;
    for (int it = 0; it < nIter; it++) {
        if (it + 1 < nIter) {
            int kn = (it + 1) * BK;
            a0 = *(const float4*)&Ap[(size_t)rowA * K + kn + slotA * 4];
            a1 = *(const float4*)&Ap[(size_t)(rowA + 64) * K + kn + slotA * 4];
            b0 = *(const float4*)&Bp[(size_t)(kn + rowB) * N + colB * 4];
            b1 = *(const float4*)&Bp[(size_t)(kn + rowB + 8) * N + colB * 4];
        }
        int buf = it & 1;
#pragma unroll
        for (int kk = 0; kk < BK; kk++) {
            float4 m0 = *(const float4*)&As[buf][kk][tr * 8];
            float4 m1 = *(const float4*)&As[buf][kk][tr * 8 + 4];
            float4 n0 = *(const float4*)&Bs[buf][kk][tc * 8];
            float4 n1 = *(const float4*)&Bs[buf][kk][tc * 8 + 4];
            float rm[8] = {m0.x, m0.y, m0.z, m0.w, m1.x, m1.y, m1.z, m1.w};
            float rn[8] = {n0.x, n0.y, n0.z, n0.w, n1.x, n1.y, n1.z, n1.w};
#pragma unroll
            for (int i = 0; i < 8; i++)
#pragma unroll
                for (int j = 0; j < 8; j++) acc[i * 8 + j] += rm[i] * rn[j];
        }
        if (it + 1 < nIter) {
            int nb = buf ^ 1;
            As[nb][slotA * 4 + 0][rowA] = a0.x;  As[nb][slotA * 4 + 1][rowA] = a0.y;
            As[nb][slotA * 4 + 2][rowA] = a0.z;  As[nb][slotA * 4 + 3][rowA] = a0.w;
            As[nb][slotA * 4 + 0][rowA + 64] = a1.x;  As[nb][slotA * 4 + 1][rowA + 64] = a1.y;
            As[nb][slotA * 4 + 2][rowA + 64] = a1.z;  As[nb][slotA * 4 + 3][rowA + 64] = a1.w;
            *(float4*)&Bs[nb][rowB][colB * 4] = b0;
            *(float4*)&Bs[nb][rowB + 8][colB * 4] = b1;
        }
        __syncthreads();
    }

#pragma unroll
    for (int i = 0; i < 8; i++) {
        int r = tr * 8 + i;
#pragma unroll
        for (int j = 0; j < 8; j += 4) {
            int c = tc * 8 + j;
            float4 v;
            v.x = acc[i * 8 + j + 0];
            v.y = acc[i * 8 + j + 1];
            v.z = acc[i * 8 + j + 2];
            v.w = acc[i * 8 + j + 3];
            if (bias) {
                v.x += bias[cCol * 128 + c + 0];
                v.y += bias[cCol * 128 + c + 1];
                v.z += bias[cCol * 128 + c + 2];
                v.w += bias[cCol * 128 + c + 3];
            }
            *(float4*)&Cp[(size_t)r * N + c] = v;
        }
    }
}

// ---------------- K2: kernel->x scores + orientation bins ----------------
__global__ __launch_bounds__(128) void k2_scores(const int* __restrict__ polar)
{
    int k = threadIdx.x;
    int xc = blockIdx.x, h = blockIdx.y, b = blockIdx.z;
    int bh = b * H_ + h;
    int xbase = xc * 512;
    __shared__ float kx_sh[64 * 32];

    float4 kq4[8];
    const float4* kqp = (const float4*)&g_QKVk[((size_t)(b * KL + k)) * TDIM + h * HD];
#pragma unroll
    for (int i = 0; i < 8; i++) kq4[i] = kqp[i];

    float bins[8];
#pragma unroll
    for (int o = 0; o < 8; o++) bins[o] = 0.f;

    float* Srow = &g_S[((size_t)bh * KL + k) * XL];
    const int* prow = &polar[((size_t)b * KL + k) * XL];

    for (int c = 0; c < 8; c++) {
        int xs = xbase + c * 64;
        __syncthreads();
        for (int g = threadIdx.x; g < 512; g += 128) {
            int row = g >> 3, c4 = g & 7;
            ((float4*)kx_sh)[g] =
                *(const float4*)&g_QKVx[((size_t)(b * XL + xs + row)) * TDIM + DIM + h * HD + c4 * 4];
        }
        __syncthreads();
        for (int j0 = 0; j0 < 64; j0 += 4) {
            float s[4];
#pragma unroll
            for (int jj = 0; jj < 4; jj++) {
                const float4* kx4 = (const float4*)&kx_sh[(j0 + jj) * 32];
                float a = 0.f;
#pragma unroll
                for (int d = 0; d < 8; d++) {
                    float4 v = kx4[d];
                    a += v.x * kq4[d].x + v.y * kq4[d].y + v.z * kq4[d].z + v.w * kq4[d].w;
                }
                s[jj] = a * SCALE;
            }
            *(float4*)&Srow[xs + j0] = make_float4(s[0], s[1], s[2], s[3]);
            int4 pp = *(const int4*)&prow[xs + j0];
            int pa[4] = {pp.x, pp.y, pp.z, pp.w};
#pragma unroll
            for (int jj = 0; jj < 4; jj++) {
                float as = fabsf(s[jj]);
#pragma unroll
                for (int o = 0; o < 8; o++) bins[o] += (pa[jj] == o) ? as : 0.f;
            }
        }
    }
    float* orow = &g_oriP[((size_t)xc * B_ * H_ * KL + bh * KL + k) * 8];
#pragma unroll
    for (int o = 0; o < 8; o++) orow[o] = bins[o];
}

// ---------------- K2c: reduce slices + argmax (first max) ----------------
__global__ void k2_argmax()
{
    int idx = blockIdx.x * blockDim.x + threadIdx.x;
    if (idx >= B_ * H_ * KL) return;
    float s[8];
#pragma unroll
    for (int o = 0; o < 8; o++) s[o] = 0.f;
#pragma unroll
    for (int xc = 0; xc < 8; xc++) {
        const float* p = &g_oriP[((size_t)xc * B_ * H_ * KL + idx) * 8];
#pragma unroll
        for (int o = 0; o < 8; o++) s[o] += p[o];
    }
    int best = 0;
    float bv = s[0];
#pragma unroll
    for (int p = 1; p < 8; p++)
        if (s[p] > bv) { bv = s[p]; best = p; }
    g_mo[idx] = best;
}

// ---------------- K3: kernel->x attention (online softmax, x-split) -------
__global__ __launch_bounds__(128) void k3_kattn(
    const int* __restrict__ rd, const int* __restrict__ polar,
    const float* __restrict__ dis_embed, const float* __restrict__ polar_emb)
{
    int k = threadIdx.x;
    int xs = blockIdx.x, h = blockIdx.y, b = blockIdx.z;
    int bh = b * H_ + h;
    __shared__ float V_sh[64 * 32];
    __shared__ float de_sh[NDIS];
    __shared__ float pe_sh[8];
    if (k < NDIS) de_sh[k] = dis_embed[k * H_ + h];
    if (k < 8) pe_sh[k] = polar_emb[k];
    int mo = g_mo[bh * KL + k];

    const float*   Srow = &g_S[((size_t)bh * KL + k) * XL];
    const int*     rrow = &rd[((size_t)b * KL + k) * XL];
    const int*     prow = &polar[((size_t)b * KL + k) * XL];
    const uint8_t* mrow = &g_maskT[((size_t)bh * KL + k) * XL];

    float m = -1e30f, l = 0.f;
    float acc[32];
#pragma unroll
    for (int d = 0; d < 32; d++) acc[d] = 0.f;

    int xbase = xs * 512;
    for (int c = 0; c < 8; c++) {
        int x0 = xbase + c * 64;
        __syncthreads();
        for (int g = threadIdx.x; g < 512; g += 128) {
            int row = g >> 3, c4 = g & 7;
            ((float4*)V_sh)[g] =
                *(const float4*)&g_QKVx[((size_t)(b * XL + x0 + row)) * TDIM + 2 * DIM + h * HD + c4 * 4];
        }
        __syncthreads();
        for (int j0 = 0; j0 < 64; j0 += 4) {
            float4 s4 = *(const float4*)&Srow[x0 + j0];
            int4 r4 = *(const int4*)&rrow[x0 + j0];
            int4 p4 = *(const int4*)&prow[x0 + j0];
            uchar4 mk4 = *(const uchar4*)&mrow[x0 + j0];
            float sv[4] = {s4.x, s4.y, s4.z, s4.w};
            int   rv[4] = {r4.x, r4.y, r4.z, r4.w};
            int   pv[4] = {p4.x, p4.y, p4.z, p4.w};
            uint8_t mv[4] = {mk4.x, mk4.y, mk4.z, mk4.w};
#pragma unroll
            for (int jj = 0; jj < 4; jj++) {
                float t = (mv[jj] ? -1e6f : sv[jj]) + de_sh[rv[jj]] + pe_sh[(pv[jj] - mo) & 7];
                float mn = fmaxf(m, t);
                float eo = __expf(m - mn);
                float w  = __expf(t - mn);
                l = l * eo + w;
                m = mn;
                const float4* vp = (const float4*)&V_sh[(j0 + jj) * 32];
#pragma unroll
                for (int d = 0; d < 8; d++) {
                    float4 v = vp[d];
                    acc[d * 4 + 0] = acc[d * 4 + 0] * eo + w * v.x;
                    acc[d * 4 + 1] = acc[d * 4 + 1] * eo + w * v.y;
                    acc[d * 4 + 2] = acc[d * 4 + 2] * eo + w * v.z;
                    acc[d * 4 + 3] = acc[d * 4 + 3] * eo + w * v.w;
                }
            }
        }
    }
    float* pp = &g_part[(((size_t)bh * 8 + xs) * KL + k) * 34];
    pp[0] = m;
    pp[1] = l;
#pragma unroll
    for (int d = 0; d < 32; d++) pp[2 + d] = acc[d];
}

// ---------------- K3c: combine x-splits -> preK ----------------
__global__ void k3_combine()
{
    int idx = blockIdx.x * blockDim.x + threadIdx.x;
    if (idx >= B_ * H_ * KL) return;
    int k = idx % KL, bh = idx / KL;
    int h = bh % H_, b = bh / H_;
    const int SSTR = KL * 34;
    const float* base = &g_part[((size_t)bh * 8) * SSTR + k * 34];
    float M = -1e30f;
#pragma unroll
    for (int s = 0; s < 8; s++) M = fmaxf(M, base[s * SSTR]);
    float es[8], L = 0.f;
#pragma unroll
    for (int s = 0; s < 8; s++) {
        es[s] = __expf(base[s * SSTR] - M);
        L += base[s * SSTR + 1] * es[s];
    }
    float invL = 1.f / L;
    float* out = &g_preK[((size_t)b * KL + k) * DIM + h * HD];
#pragma unroll
    for (int d = 0; d < 32; d++) {
        float a = 0.f;
#pragma unroll
        for (int s = 0; s < 8; s++) a += base[s * SSTR + 2 + d] * es[s];
        out[d] = a * invL;
    }
}

// ---------------- K4: x->kernel attention (fully fused) ----------------
__global__ __launch_bounds__(256) void k4_xattn(
    const int* __restrict__ rd, const int* __restrict__ polar,
    const float* __restrict__ dis_embed, const float* __restrict__ polar_emb)
{
    __shared__ float kk_sh[KL * HD];
    __shared__ float kv_sh[KL * HD];
    __shared__ float de_sh[NDIS];
    __shared__ float pe_sh[8];
    __shared__ int   mo_sh[KL];
    int tid = threadIdx.x;
    int xc = blockIdx.x, h = blockIdx.y, b = blockIdx.z;
    int bh = b * H_ + h;

    for (int g = tid; g < KL * HD / 4; g += 256) {
        int row = g >> 3, c4 = g & 7;
        ((float4*)kk_sh)[g] =
            *(const float4*)&g_QKVk[((size_t)(b * KL + row)) * TDIM + DIM + h * HD + c4 * 4];
        ((float4*)kv_sh)[g] =
            *(const float4*)&g_QKVk[((size_t)(b * KL + row)) * TDIM + 2 * DIM + h * HD + c4 * 4];
    }
    if (tid < NDIS) de_sh[tid] = dis_embed[tid * H_ + h];
    if (tid < 8) pe_sh[tid] = polar_emb[tid];
    if (tid < KL) mo_sh[tid] = g_mo[bh * KL + tid];
    __syncthreads();

    int x = xc * 256 + tid;
    float4 q4[8];
    const float4* qp = (const float4*)&g_QKVx[((size_t)(b * XL + x)) * TDIM + h * HD];
#pragma unroll
    for (int i = 0; i < 8; i++) q4[i] = qp[i];
    const uint8_t* mbase = &g_maskT[(size_t)bh * KL * XL + x];   // + kidx*XL (coalesced)

    float m = -1e30f, l = 0.f;
    float acc[32];
#pragma unroll
    for (int d = 0; d < 32; d++) acc[d] = 0.f;

    for (int k0 = 0; k0 < KL; k0 += 4) {
#pragma unroll
        for (int ki = 0; ki < 4; ki++) {
            int kidx = k0 + ki;
            const float4* kkp = (const float4*)&kk_sh[kidx * HD];
            float s = 0.f;
#pragma unroll
            for (int d = 0; d < 8; d++) {
                float4 a = kkp[d];
                s += a.x * q4[d].x + a.y * q4[d].y + a.z * q4[d].z + a.w * q4[d].w;
            }
            s *= SCALE;
            int rv = rd[((size_t)b * KL + kidx) * XL + x];
            int pv = polar[((size_t)b * KL + kidx) * XL + x];
            uint8_t mk = mbase[(size_t)kidx * XL];
            float t = (mk ? -1e9f : s) + de_sh[rv] + pe_sh[(pv - mo_sh[kidx]) & 7];
            float mn = fmaxf(m, t);
            float eo = __expf(m - mn);
            float w  = __expf(t - mn);
            l = l * eo + w;
            m = mn;
            const float4* vp = (const float4*)&kv_sh[kidx * HD];
#pragma unroll
            for (int d = 0; d < 8; d++) {
                float4 v = vp[d];
                acc[d * 4 + 0] = acc[d * 4 + 0] * eo + w * v.x;
                acc[d * 4 + 1] = acc[d * 4 + 1] * eo + w * v.y;
                acc[d * 4 + 2] = acc[d * 4 + 2] * eo + w * v.z;
                acc[d * 4 + 3] = acc[d * 4 + 3] * eo + w * v.w;
            }
        }
    }
    float invl = 1.f / l;
    float* out = &g_preX[((size_t)(b * XL + x)) * DIM + h * HD];
#pragma unroll
    for (int d = 0; d < 8; d++) {
        float4 v;
        v.x = acc[d * 4 + 0] * invl;
        v.y = acc[d * 4 + 1] * invl;
        v.z = acc[d * 4 + 2] * invl;
        v.w = acc[d * 4 + 3] * invl;
        *(float4*)&out[d * 4] = v;
    }
}

// ---------------- host launcher ----------------
extern "C" void kernel_launch(void* const* d_in, const int* in_sizes, int n_in,
                              void* d_out, int out_size)
{
    const float* x     = (const float*)d_in[0];
    const float* kern  = (const float*)d_in[1];
    const int*   rd    = (const int*)d_in[2];
    const int*   polar = (const int*)d_in[3];
    const void*  mask  = d_in[4];
    const float* Wqkv  = (const float*)d_in[5];
    const float* dis   = (const float*)d_in[6];
    const float* pemb  = (const float*)d_in[7];
    const float* Wproj = (const float*)d_in[8];
    const float* bproj = (const float*)d_in[9];
    float* out = (float*)d_out;

    float* pQKVx; cudaGetSymbolAddress((void**)&pQKVx, g_QKVx);
    float* pQKVk; cudaGetSymbolAddress((void**)&pQKVk, g_QKVk);
    float* pPreX; cudaGetSymbolAddress((void**)&pPreX, g_preX);
    float* pPreK; cudaGetSymbolAddress((void**)&pPreK, g_preK);

    // mask dtype probe + fused canonicalize/transpose
    det_reset<<<1, 32>>>();
    det_scan<<<4096, 256>>>((const unsigned*)mask);
    conv_transpose_mask<<<dim3(XL / 128, KL / 32, B_ * H_), dim3(32, 8)>>>(mask);

    // QKV projections
    sgemm_db<<<dim3(TDIM / 128, (B_ * XL) / 128), 256>>>(x, Wqkv, nullptr, pQKVx, B_ * XL, TDIM, DIM);
    sgemm_db<<<dim3(TDIM / 128, (B_ * KL) / 128), 256>>>(kern, Wqkv, nullptr, pQKVk, B_ * KL, TDIM, DIM);

    // kernel->x scores + orientation
    k2_scores<<<dim3(XL / 512, H_, B_), 128>>>(polar);
    k2_argmax<<<(B_ * H_ * KL + 255) / 256, 256>>>();

    // kernel->x attention
    k3_kattn<<<dim3(8, H_, B_), 128>>>(rd, polar, dis, pemb);
    k3_combine<<<(B_ * H_ * KL + 255) / 256, 256>>>();

    // x->kernel attention
    k4_xattn<<<dim3(XL / 256, H_, B_), 256>>>(rd, polar, dis, pemb);

    // output projections
    sgemm_db<<<dim3(DIM / 128, (B_ * XL) / 128), 256>>>(pPreX, Wproj, bproj, out, B_ * XL, DIM, DIM);
    sgemm_db<<<dim3(DIM / 128, (B_ * KL) / 128), 256>>>(pPreK, Wproj, bproj, out + (size_t)B_ * XL * DIM, B_ * KL, DIM, DIM);
}

// round 5
// speedup vs baseline: 1.7014x; 1.7014x over previous
#include <cuda_runtime.h>
#include <cstdint>

#define B_    4
#define KL    128
#define XL    4096
#define DIM   256
#define H_    8
#define HD    32
#define PB    8
#define NDIS  66
#define TDIM  768           // 3*DIM
#define SCALE 0.17677669529663687f
#define NMASK (B_ * H_ * XL * KL)

// ---------------- scratch (device globals: no allocs allowed) ----------------
__device__ float    g_QKVx[B_ * XL * TDIM];
__device__ float    g_QKVk[B_ * KL * TDIM];
__device__ float    g_S[(size_t)B_ * H_ * KL * XL];
__device__ float    g_oriP[8 * B_ * H_ * KL * PB];
__device__ int      g_mo[B_ * H_ * KL];
__device__ uint8_t  g_maskC[(size_t)NMASK];            // canonical u8 (b,h,x,k)
__device__ uint8_t  g_maskT[(size_t)NMASK];            // transposed (b,h,k,x)
__device__ float    g_part[B_ * H_ * 8 * KL * 34];
__device__ float    g_preK[B_ * KL * DIM];
__device__ float    g_preX[B_ * XL * DIM];
__device__ unsigned g_flags;

// ---------------- mask dtype probe ----------------
__global__ void det_reset() { if (threadIdx.x == 0) g_flags = 0u; }

__global__ void det_scan(const unsigned* __restrict__ w)
{
    int i = blockIdx.x * blockDim.x + threadIdx.x;
    unsigned v = w[i];
    unsigned f = 0;
    if (v == 0x3F800000u) f |= 1u;
    else if (v != 0u && v != 1u) f |= 2u;
    for (int o = 16; o > 0; o >>= 1) f |= __shfl_xor_sync(0xffffffffu, f, o);
    if ((threadIdx.x & 31) == 0 && f) atomicOr(&g_flags, f);
}

__global__ void conv_mask(const void* __restrict__ m)
{
    unsigned flags = g_flags;
    int mode = (flags & 1u) ? 2 : ((flags & 2u) ? 0 : 1);
    int i = (blockIdx.x * blockDim.x + threadIdx.x) * 4;
    if (i >= NMASK) return;
    uchar4 o;
    if (mode == 0) {
        uchar4 v = *(const uchar4*)((const uint8_t*)m + i);
        o.x = v.x != 0; o.y = v.y != 0; o.z = v.z != 0; o.w = v.w != 0;
    } else if (mode == 1) {
        int4 v = *(const int4*)((const int*)m + i);
        o.x = v.x != 0; o.y = v.y != 0; o.z = v.z != 0; o.w = v.w != 0;
    } else {
        float4 v = *(const float4*)((const float*)m + i);
        o.x = v.x != 0.f; o.y = v.y != 0.f; o.z = v.z != 0.f; o.w = v.w != 0.f;
    }
    *(uchar4*)&g_maskC[i] = o;
}

__global__ void transpose_mask()
{
    __shared__ uint8_t tile[32][33];
    int bh = blockIdx.z;
    int x0 = blockIdx.x * 32, k0 = blockIdx.y * 32;
    int tx = threadIdx.x, ty = threadIdx.y;
#pragma unroll
    for (int i = ty; i < 32; i += 8)
        tile[i][tx] = g_maskC[((size_t)bh * XL + x0 + i) * KL + k0 + tx];
    __syncthreads();
#pragma unroll
    for (int i = ty; i < 32; i += 8)
        g_maskT[((size_t)bh * KL + k0 + i) * XL + x0 + tx] = tile[tx][i];
}

// ---------------- 3xTF32 tensor-core GEMM ----------------
// C(MxN) = A(MxK) @ B(KxN) [+bias], all fp32 row-major.
// Block 128x128, BK=32, 256 threads (8 warps as 2(m) x 4(n), warp tile 64x32).
__device__ __forceinline__ void split_tf32(float x, uint32_t& hi, uint32_t& lo)
{
    asm("cvt.rna.tf32.f32 %0, %1;" : "=r"(hi) : "f"(x));
    float r = x - __uint_as_float(hi);
    asm("cvt.rna.tf32.f32 %0, %1;" : "=r"(lo) : "f"(r));
}

__device__ __forceinline__ void mma_tf32(float* c, const uint32_t* a, uint32_t b0, uint32_t b1)
{
    asm("mma.sync.aligned.m16n8k8.row.col.f32.tf32.tf32.f32 "
        "{%0,%1,%2,%3}, {%4,%5,%6,%7}, {%8,%9}, {%0,%1,%2,%3};"
        : "+f"(c[0]), "+f"(c[1]), "+f"(c[2]), "+f"(c[3])
        : "r"(a[0]), "r"(a[1]), "r"(a[2]), "r"(a[3]), "r"(b0), "r"(b1));
}

__global__ __launch_bounds__(256, 2) void gemm_tf32(
    const float* __restrict__ A, const float* __restrict__ Bm,
    const float* __restrict__ bias, float* __restrict__ C,
    int M, int N, int K)
{
    __shared__ float As[128][36];   // [m][k], pad 36 -> conflict-free frag reads
    __shared__ float Bs[32][132];   // [k][n]
    int tid = threadIdx.x;
    int wid = tid >> 5, lane = tid & 31;
    int quad = lane >> 2, qt = lane & 3;
    int wm = wid & 1, wn = wid >> 1;          // 2 x 4 warp grid
    int cCol = blockIdx.x, cRow = blockIdx.y;
    const float* Ap = A + (size_t)cRow * 128 * K;
    const float* Bp = Bm + cCol * 128;

    float acc[4][4][4];
#pragma unroll
    for (int i = 0; i < 4; i++)
#pragma unroll
        for (int j = 0; j < 4; j++)
#pragma unroll
            for (int c = 0; c < 4; c++) acc[i][j][c] = 0.f;

    for (int k0 = 0; k0 < K; k0 += 32) {
        // load A tile 128x32 (1024 f4, 4 per thread)
#pragma unroll
        for (int j = 0; j < 4; j++) {
            int f = tid + 256 * j;
            int r = f >> 3, s = f & 7;
            float4 v = *(const float4*)&Ap[(size_t)r * K + k0 + s * 4];
            *(float4*)&As[r][s * 4] = v;
        }
        // load B tile 32x128
#pragma unroll
        for (int j = 0; j < 4; j++) {
            int f = tid + 256 * j;
            int r = f >> 5, s = f & 31;
            float4 v = *(const float4*)&Bp[(size_t)(k0 + r) * N + s * 4];
            *(float4*)&Bs[r][s * 4] = v;
        }
        __syncthreads();

#pragma unroll
        for (int kk = 0; kk < 4; kk++) {
            uint32_t ahi[4][4], alo[4][4];
#pragma unroll
            for (int mi = 0; mi < 4; mi++) {
                int ar = wm * 64 + mi * 16 + quad;
                int ac = kk * 8 + qt;
                split_tf32(As[ar][ac],          ahi[mi][0], alo[mi][0]);
                split_tf32(As[ar + 8][ac],      ahi[mi][1], alo[mi][1]);
                split_tf32(As[ar][ac + 4],      ahi[mi][2], alo[mi][2]);
                split_tf32(As[ar + 8][ac + 4],  ahi[mi][3], alo[mi][3]);
            }
#pragma unroll
            for (int ni = 0; ni < 4; ni++) {
                int bc = wn * 32 + ni * 8 + quad;
                int br = kk * 8 + qt;
                uint32_t bh0, bh1, bl0, bl1;
                split_tf32(Bs[br][bc],     bh0, bl0);
                split_tf32(Bs[br + 4][bc], bh1, bl1);
#pragma unroll
                for (int mi = 0; mi < 4; mi++) {
                    mma_tf32(acc[mi][ni], ahi[mi], bh0, bh1);
                    mma_tf32(acc[mi][ni], alo[mi], bh0, bh1);
                    mma_tf32(acc[mi][ni], ahi[mi], bl0, bl1);
                }
            }
        }
        __syncthreads();
    }

    // epilogue
#pragma unroll
    for (int mi = 0; mi < 4; mi++) {
#pragma unroll
        for (int ni = 0; ni < 4; ni++) {
            int r0 = cRow * 128 + wm * 64 + mi * 16 + quad;
            int c0 = cCol * 128 + wn * 32 + ni * 8 + 2 * qt;
            float b0 = bias ? bias[c0] : 0.f;
            float b1 = bias ? bias[c0 + 1] : 0.f;
            float2 v01 = make_float2(acc[mi][ni][0] + b0, acc[mi][ni][1] + b1);
            float2 v23 = make_float2(acc[mi][ni][2] + b0, acc[mi][ni][3] + b1);
            *(float2*)&C[(size_t)r0 * N + c0] = v01;
            *(float2*)&C[(size_t)(r0 + 8) * N + c0] = v23;
        }
    }
}

// ---------------- K2: kernel->x scores + orientation bins ----------------
__global__ __launch_bounds__(128) void k2_scores(const int* __restrict__ polar)
{
    int k = threadIdx.x;
    int xc = blockIdx.x, h = blockIdx.y, b = blockIdx.z;
    int bh = b * H_ + h;
    int xbase = xc * 512;
    __shared__ float kx_sh[64 * 32];

    float4 kq4[8];
    const float4* kqp = (const float4*)&g_QKVk[((size_t)(b * KL + k)) * TDIM + h * HD];
#pragma unroll
    for (int i = 0; i < 8; i++) kq4[i] = kqp[i];

    float bins[8];
#pragma unroll
    for (int o = 0; o < 8; o++) bins[o] = 0.f;

    float* Srow = &g_S[((size_t)bh * KL + k) * XL];
    const int* prow = &polar[((size_t)b * KL + k) * XL];

    for (int c = 0; c < 8; c++) {
        int xs = xbase + c * 64;
        __syncthreads();
        for (int g = threadIdx.x; g < 512; g += 128) {
            int row = g >> 3, c4 = g & 7;
            ((float4*)kx_sh)[g] =
                *(const float4*)&g_QKVx[((size_t)(b * XL + xs + row)) * TDIM + DIM + h * HD + c4 * 4];
        }
        __syncthreads();
        for (int j0 = 0; j0 < 64; j0 += 4) {
            float s[4];
#pragma unroll
            for (int jj = 0; jj < 4; jj++) {
                const float4* kx4 = (const float4*)&kx_sh[(j0 + jj) * 32];
                float a = 0.f;
#pragma unroll
                for (int d = 0; d < 8; d++) {
                    float4 v = kx4[d];
                    a += v.x * kq4[d].x + v.y * kq4[d].y + v.z * kq4[d].z + v.w * kq4[d].w;
                }
                s[jj] = a * SCALE;
            }
            *(float4*)&Srow[xs + j0] = make_float4(s[0], s[1], s[2], s[3]);
            int4 pp = *(const int4*)&prow[xs + j0];
            int pa[4] = {pp.x, pp.y, pp.z, pp.w};
#pragma unroll
            for (int jj = 0; jj < 4; jj++) {
                float as = fabsf(s[jj]);
#pragma unroll
                for (int o = 0; o < 8; o++) bins[o] += (pa[jj] == o) ? as : 0.f;
            }
        }
    }
    float* orow = &g_oriP[((size_t)xc * B_ * H_ * KL + bh * KL + k) * 8];
#pragma unroll
    for (int o = 0; o < 8; o++) orow[o] = bins[o];
}

// ---------------- K2c: reduce slices + argmax ----------------
__global__ void k2_argmax()
{
    int idx = blockIdx.x * blockDim.x + threadIdx.x;
    if (idx >= B_ * H_ * KL) return;
    float s[8];
#pragma unroll
    for (int o = 0; o < 8; o++) s[o] = 0.f;
#pragma unroll
    for (int xc = 0; xc < 8; xc++) {
        const float* p = &g_oriP[((size_t)xc * B_ * H_ * KL + idx) * 8];
#pragma unroll
        for (int o = 0; o < 8; o++) s[o] += p[o];
    }
    int best = 0;
    float bv = s[0];
#pragma unroll
    for (int p = 1; p < 8; p++)
        if (s[p] > bv) { bv = s[p]; best = p; }
    g_mo[idx] = best;
}

// ---------------- K3: kernel->x attention ----------------
__global__ __launch_bounds__(128) void k3_kattn(
    const int* __restrict__ rd, const int* __restrict__ polar,
    const float* __restrict__ dis_embed, const float* __restrict__ polar_emb)
{
    int k = threadIdx.x;
    int xs = blockIdx.x, h = blockIdx.y, b = blockIdx.z;
    int bh = b * H_ + h;
    __shared__ float V_sh[64 * 32];
    __shared__ float de_sh[NDIS];
    __shared__ float pe_sh[8];
    if (k < NDIS) de_sh[k] = dis_embed[k * H_ + h];
    if (k < 8) pe_sh[k] = polar_emb[k];
    int mo = g_mo[bh * KL + k];

    const float*   Srow = &g_S[((size_t)bh * KL + k) * XL];
    const int*     rrow = &rd[((size_t)b * KL + k) * XL];
    const int*     prow = &polar[((size_t)b * KL + k) * XL];
    const uint8_t* mrow = &g_maskT[((size_t)bh * KL + k) * XL];

    float m = -1e30f, l = 0.f;
    float acc[32];
#pragma unroll
    for (int d = 0; d < 32; d++) acc[d] = 0.f;

    int xbase = xs * 512;
    for (int c = 0; c < 8; c++) {
        int x0 = xbase + c * 64;
        __syncthreads();
        for (int g = threadIdx.x; g < 512; g += 128) {
            int row = g >> 3, c4 = g & 7;
            ((float4*)V_sh)[g] =
                *(const float4*)&g_QKVx[((size_t)(b * XL + x0 + row)) * TDIM + 2 * DIM + h * HD + c4 * 4];
        }
        __syncthreads();
        for (int j0 = 0; j0 < 64; j0 += 4) {
            float4 s4 = *(const float4*)&Srow[x0 + j0];
            int4 r4 = *(const int4*)&rrow[x0 + j0];
            int4 p4 = *(const int4*)&prow[x0 + j0];
            uchar4 mk4 = *(const uchar4*)&mrow[x0 + j0];
            float sv[4] = {s4.x, s4.y, s4.z, s4.w};
            int   rv[4] = {r4.x, r4.y, r4.z, r4.w};
            int   pv[4] = {p4.x, p4.y, p4.z, p4.w};
            uint8_t mv[4] = {mk4.x, mk4.y, mk4.z, mk4.w};
#pragma unroll
            for (int jj = 0; jj < 4; jj++) {
                float t = (mv[jj] ? -1e6f : sv[jj]) + de_sh[rv[jj]] + pe_sh[(pv[jj] - mo) & 7];
                float mn = fmaxf(m, t);
                float eo = __expf(m - mn);
                float w  = __expf(t - mn);
                l = l * eo + w;
                m = mn;
                const float4* vp = (const float4*)&V_sh[(j0 + jj) * 32];
#pragma unroll
                for (int d = 0; d < 8; d++) {
                    float4 v = vp[d];
                    acc[d * 4 + 0] = acc[d * 4 + 0] * eo + w * v.x;
                    acc[d * 4 + 1] = acc[d * 4 + 1] * eo + w * v.y;
                    acc[d * 4 + 2] = acc[d * 4 + 2] * eo + w * v.z;
                    acc[d * 4 + 3] = acc[d * 4 + 3] * eo + w * v.w;
                }
            }
        }
    }
    float* pp = &g_part[(((size_t)bh * 8 + xs) * KL + k) * 34];
    pp[0] = m;
    pp[1] = l;
#pragma unroll
    for (int d = 0; d < 32; d++) pp[2 + d] = acc[d];
}

// ---------------- K3c: combine x-splits -> preK ----------------
__global__ void k3_combine()
{
    int idx = blockIdx.x * blockDim.x + threadIdx.x;
    if (idx >= B_ * H_ * KL) return;
    int k = idx % KL, bh = idx / KL;
    int h = bh % H_, b = bh / H_;
    const int SSTR = KL * 34;
    const float* base = &g_part[((size_t)bh * 8) * SSTR + k * 34];
    float M = -1e30f;
#pragma unroll
    for (int s = 0; s < 8; s++) M = fmaxf(M, base[s * SSTR]);
    float es[8], L = 0.f;
#pragma unroll
    for (int s = 0; s < 8; s++) {
        es[s] = __expf(base[s * SSTR] - M);
        L += base[s * SSTR + 1] * es[s];
    }
    float invL = 1.f / L;
    float* out = &g_preK[((size_t)b * KL + k) * DIM + h * HD];
#pragma unroll
    for (int d = 0; d < 32; d++) {
        float a = 0.f;
#pragma unroll
        for (int s = 0; s < 8; s++) a += base[s * SSTR + 2 + d] * es[s];
        out[d] = a * invL;
    }
}

// ---------------- K4: x->kernel attention ----------------
__global__ __launch_bounds__(256) void k4_xattn(
    const int* __restrict__ rd, const int* __restrict__ polar,
    const float* __restrict__ dis_embed, const float* __restrict__ polar_emb)
{
    __shared__ float kk_sh[KL * HD];
    __shared__ float kv_sh[KL * HD];
    __shared__ float de_sh[NDIS];
    __shared__ float pe_sh[8];
    __shared__ int   mo_sh[KL];
    int tid = threadIdx.x;
    int xc = blockIdx.x, h = blockIdx.y, b = blockIdx.z;
    int bh = b * H_ + h;

    for (int g = tid; g < KL * HD / 4; g += 256) {
        int row = g >> 3, c4 = g & 7;
        ((float4*)kk_sh)[g] =
            *(const float4*)&g_QKVk[((size_t)(b * KL + row)) * TDIM + DIM + h * HD + c4 * 4];
        ((float4*)kv_sh)[g] =
            *(const float4*)&g_QKVk[((size_t)(b * KL + row)) * TDIM + 2 * DIM + h * HD + c4 * 4];
    }
    if (tid < NDIS) de_sh[tid] = dis_embed[tid * H_ + h];
    if (tid < 8) pe_sh[tid] = polar_emb[tid];
    if (tid < KL) mo_sh[tid] = g_mo[bh * KL + tid];
    __syncthreads();

    int x = xc * 256 + tid;
    float4 q4[8];
    const float4* qp = (const float4*)&g_QKVx[((size_t)(b * XL + x)) * TDIM + h * HD];
#pragma unroll
    for (int i = 0; i < 8; i++) q4[i] = qp[i];
    const uint8_t* mrow = &g_maskC[((size_t)bh * XL + x) * KL];

    float m = -1e30f, l = 0.f;
    float acc[32];
#pragma unroll
    for (int d = 0; d < 32; d++) acc[d] = 0.f;

    for (int k0 = 0; k0 < KL; k0 += 4) {
        uchar4 mk4 = *(const uchar4*)&mrow[k0];
        uint8_t mv[4] = {mk4.x, mk4.y, mk4.z, mk4.w};
#pragma unroll
        for (int ki = 0; ki < 4; ki++) {
            int kidx = k0 + ki;
            const float4* kkp = (const float4*)&kk_sh[kidx * HD];
            float s = 0.f;
#pragma unroll
            for (int d = 0; d < 8; d++) {
                float4 a = kkp[d];
                s += a.x * q4[d].x + a.y * q4[d].y + a.z * q4[d].z + a.w * q4[d].w;
            }
            s *= SCALE;
            int rv = rd[((size_t)b * KL + kidx) * XL + x];
            int pv = polar[((size_t)b * KL + kidx) * XL + x];
            float t = (mv[ki] ? -1e9f : s) + de_sh[rv] + pe_sh[(pv - mo_sh[kidx]) & 7];
            float mn = fmaxf(m, t);
            float eo = __expf(m - mn);
            float w  = __expf(t - mn);
            l = l * eo + w;
            m = mn;
            const float4* vp = (const float4*)&kv_sh[kidx * HD];
#pragma unroll
            for (int d = 0; d < 8; d++) {
                float4 v = vp[d];
                acc[d * 4 + 0] = acc[d * 4 + 0] * eo + w * v.x;
                acc[d * 4 + 1] = acc[d * 4 + 1] * eo + w * v.y;
                acc[d * 4 + 2] = acc[d * 4 + 2] * eo + w * v.z;
                acc[d * 4 + 3] = acc[d * 4 + 3] * eo + w * v.w;
            }
        }
    }
    float invl = 1.f / l;
    float* out = &g_preX[((size_t)(b * XL + x)) * DIM + h * HD];
#pragma unroll
    for (int d = 0; d < 8; d++) {
        float4 v;
        v.x = acc[d * 4 + 0] * invl;
        v.y = acc[d * 4 + 1] * invl;
        v.z = acc[d * 4 + 2] * invl;
        v.w = acc[d * 4 + 3] * invl;
        *(float4*)&out[d * 4] = v;
    }
}

// ---------------- host launcher ----------------
extern "C" void kernel_launch(void* const* d_in, const int* in_sizes, int n_in,
                              void* d_out, int out_size)
{
    const float* x     = (const float*)d_in[0];
    const float* kern  = (const float*)d_in[1];
    const int*   rd    = (const int*)d_in[2];
    const int*   polar = (const int*)d_in[3];
    const void*  mask  = d_in[4];
    const float* Wqkv  = (const float*)d_in[5];
    const float* dis   = (const float*)d_in[6];
    const float* pemb  = (const float*)d_in[7];
    const float* Wproj = (const float*)d_in[8];
    const float* bproj = (const float*)d_in[9];
    float* out = (float*)d_out;

    float* pQKVx; cudaGetSymbolAddress((void**)&pQKVx, g_QKVx);
    float* pQKVk; cudaGetSymbolAddress((void**)&pQKVk, g_QKVk);
    float* pPreX; cudaGetSymbolAddress((void**)&pPreX, g_preX);
    float* pPreK; cudaGetSymbolAddress((void**)&pPreK, g_preK);

    // mask dtype probe + canonicalization (round-3 proven path)
    det_reset<<<1, 32>>>();
    det_scan<<<4096, 256>>>((const unsigned*)mask);
    conv_mask<<<(NMASK / 4 + 255) / 256, 256>>>(mask);
    transpose_mask<<<dim3(XL / 32, KL / 32, B_ * H_), dim3(32, 8)>>>();

    // QKV projections (3xTF32 tensor cores)
    gemm_tf32<<<dim3(TDIM / 128, (B_ * XL) / 128), 256>>>(x, Wqkv, nullptr, pQKVx, B_ * XL, TDIM, DIM);
    gemm_tf32<<<dim3(TDIM / 128, (B_ * KL) / 128), 256>>>(kern, Wqkv, nullptr, pQKVk, B_ * KL, TDIM, DIM);

    // kernel->x scores + orientation
    k2_scores<<<dim3(XL / 512, H_, B_), 128>>>(polar);
    k2_argmax<<<(B_ * H_ * KL + 255) / 256, 256>>>();

    // kernel->x attention
    k3_kattn<<<dim3(8, H_, B_), 128>>>(rd, polar, dis, pemb);
    k3_combine<<<(B_ * H_ * KL + 255) / 256, 256>>>();

    // x->kernel attention
    k4_xattn<<<dim3(XL / 256, H_, B_), 256>>>(rd, polar, dis, pemb);

    // output projections
    gemm_tf32<<<dim3(DIM / 128, (B_ * XL) / 128), 256>>>(pPreX, Wproj, bproj, out, B_ * XL, DIM, DIM);
    gemm_tf32<<<dim3(DIM / 128, (B_ * KL) / 128), 256>>>(pPreK, Wproj, bproj, out + (size_t)B_ * XL * DIM, B_ * KL, DIM, DIM);
}

// round 6
// speedup vs baseline: 1.7121x; 1.0063x over previous
#include <cuda_runtime.h>
#include <cstdint>

#define B_    4
#define KL    128
#define XL    4096
#define DIM   256
#define H_    8
#define HD    32
#define PB    8
#define NDIS  66
#define TDIM  768           // 3*DIM
#define SCALE 0.17677669529663687f
#define NMASK (B_ * H_ * XL * KL)

// ---------------- scratch (device globals) ----------------
__device__ float    g_QKVx[B_ * XL * TDIM];
__device__ float    g_QKVk[B_ * KL * TDIM];
__device__ unsigned short g_pack[(size_t)NMASK];       // (b,h,k,x): rd | polar<<7 | mask<<10
__device__ float    g_oriP[8 * B_ * H_ * KL * PB];
__device__ int      g_mo[B_ * H_ * KL];
__device__ float    g_part[B_ * H_ * 8 * KL * 34];
__device__ float    g_preK[B_ * KL * DIM];
__device__ float    g_preX[B_ * XL * DIM];
__device__ unsigned g_flags;

// ---------------- mask dtype probe ----------------
__global__ void det_reset() { if (threadIdx.x == 0) g_flags = 0u; }

__global__ void det_scan(const unsigned* __restrict__ w)
{
    int i = blockIdx.x * blockDim.x + threadIdx.x;
    unsigned v = w[i];
    unsigned f = 0;
    if (v == 0x3F800000u) f |= 1u;
    else if (v != 0u && v != 1u) f |= 2u;
    for (int o = 16; o > 0; o >>= 1) f |= __shfl_xor_sync(0xffffffffu, f, o);
    if ((threadIdx.x & 31) == 0 && f) atomicOr(&g_flags, f);
}

// ---------------- pack16: rd+polar+mask(transposed) -> u16 (b,h,k,x) ------
// grid (XL/64, KL/32, B_), block (32,8); loops h internally (rd/polar read once)
__global__ void pack16(const void* __restrict__ mask,
                       const int* __restrict__ rd, const int* __restrict__ polar)
{
    __shared__ unsigned short rp_sh[32][66];   // [k][x]
    __shared__ uint8_t m_sh[64][36];           // [x][k]
    unsigned flags = g_flags;
    int mode = (flags & 1u) ? 2 : ((flags & 2u) ? 0 : 1);  // 0=u8 1=i32 2=f32
    int x0 = blockIdx.x * 64, k0 = blockIdx.y * 32, b = blockIdx.z;
    int tx = threadIdx.x, ty = threadIdx.y;

#pragma unroll
    for (int ki = ty; ki < 32; ki += 8) {
        size_t rowb = ((size_t)(b * KL + k0 + ki)) * XL + x0;
#pragma unroll
        for (int xx = tx; xx < 64; xx += 32) {
            int r = rd[rowb + xx];
            int p = polar[rowb + xx];
            rp_sh[ki][xx] = (unsigned short)(r | (p << 7));
        }
    }
    for (int h = 0; h < H_; h++) {
        size_t mb = ((size_t)((b * H_ + h)) * XL + x0) * KL + k0;
#pragma unroll
        for (int xi = ty; xi < 64; xi += 8) {
            uint8_t v;
            if (mode == 1)      v = ((const int*)mask)[mb + (size_t)xi * KL + tx] != 0;
            else if (mode == 2) v = ((const float*)mask)[mb + (size_t)xi * KL + tx] != 0.f;
            else                v = ((const uint8_t*)mask)[mb + (size_t)xi * KL + tx] != 0;
            m_sh[xi][tx] = v;
        }
        __syncthreads();
        size_t ob = ((size_t)((b * H_ + h) * KL + k0)) * XL + x0;
#pragma unroll
        for (int ki = ty; ki < 32; ki += 8)
#pragma unroll
            for (int xx = tx; xx < 64; xx += 32)
                g_pack[ob + (size_t)ki * XL + xx] =
                    (unsigned short)(rp_sh[ki][xx] | ((unsigned short)m_sh[xx][ki] << 10));
        __syncthreads();
    }
}

// ---------------- 3xTF32 tensor-core GEMM (unchanged, proven) -------------
__device__ __forceinline__ void split_tf32(float x, uint32_t& hi, uint32_t& lo)
{
    asm("cvt.rna.tf32.f32 %0, %1;" : "=r"(hi) : "f"(x));
    float r = x - __uint_as_float(hi);
    asm("cvt.rna.tf32.f32 %0, %1;" : "=r"(lo) : "f"(r));
}

__device__ __forceinline__ void mma_tf32(float* c, const uint32_t* a, uint32_t b0, uint32_t b1)
{
    asm("mma.sync.aligned.m16n8k8.row.col.f32.tf32.tf32.f32 "
        "{%0,%1,%2,%3}, {%4,%5,%6,%7}, {%8,%9}, {%0,%1,%2,%3};"
        : "+f"(c[0]), "+f"(c[1]), "+f"(c[2]), "+f"(c[3])
        : "r"(a[0]), "r"(a[1]), "r"(a[2]), "r"(a[3]), "r"(b0), "r"(b1));
}

__global__ __launch_bounds__(256, 2) void gemm_tf32(
    const float* __restrict__ A, const float* __restrict__ Bm,
    const float* __restrict__ bias, float* __restrict__ C,
    int M, int N, int K)
{
    __shared__ float As[128][36];
    __shared__ float Bs[32][132];
    int tid = threadIdx.x;
    int wid = tid >> 5, lane = tid & 31;
    int quad = lane >> 2, qt = lane & 3;
    int wm = wid & 1, wn = wid >> 1;
    int cCol = blockIdx.x, cRow = blockIdx.y;
    const float* Ap = A + (size_t)cRow * 128 * K;
    const float* Bp = Bm + cCol * 128;

    float acc[4][4][4];
#pragma unroll
    for (int i = 0; i < 4; i++)
#pragma unroll
        for (int j = 0; j < 4; j++)
#pragma unroll
            for (int c = 0; c < 4; c++) acc[i][j][c] = 0.f;

    for (int k0 = 0; k0 < K; k0 += 32) {
#pragma unroll
        for (int j = 0; j < 4; j++) {
            int f = tid + 256 * j;
            int r = f >> 3, s = f & 7;
            float4 v = *(const float4*)&Ap[(size_t)r * K + k0 + s * 4];
            *(float4*)&As[r][s * 4] = v;
        }
#pragma unroll
        for (int j = 0; j < 4; j++) {
            int f = tid + 256 * j;
            int r = f >> 5, s = f & 31;
            float4 v = *(const float4*)&Bp[(size_t)(k0 + r) * N + s * 4];
            *(float4*)&Bs[r][s * 4] = v;
        }
        __syncthreads();

#pragma unroll
        for (int kk = 0; kk < 4; kk++) {
            uint32_t ahi[4][4], alo[4][4];
#pragma unroll
            for (int mi = 0; mi < 4; mi++) {
                int ar = wm * 64 + mi * 16 + quad;
                int ac = kk * 8 + qt;
                split_tf32(As[ar][ac],          ahi[mi][0], alo[mi][0]);
                split_tf32(As[ar + 8][ac],      ahi[mi][1], alo[mi][1]);
                split_tf32(As[ar][ac + 4],      ahi[mi][2], alo[mi][2]);
                split_tf32(As[ar + 8][ac + 4],  ahi[mi][3], alo[mi][3]);
            }
#pragma unroll
            for (int ni = 0; ni < 4; ni++) {
                int bc = wn * 32 + ni * 8 + quad;
                int br = kk * 8 + qt;
                uint32_t bh0, bh1, bl0, bl1;
                split_tf32(Bs[br][bc],     bh0, bl0);
                split_tf32(Bs[br + 4][bc], bh1, bl1);
#pragma unroll
                for (int mi = 0; mi < 4; mi++) {
                    mma_tf32(acc[mi][ni], ahi[mi], bh0, bh1);
                    mma_tf32(acc[mi][ni], alo[mi], bh0, bh1);
                    mma_tf32(acc[mi][ni], ahi[mi], bl0, bl1);
                }
            }
        }
        __syncthreads();
    }

#pragma unroll
    for (int mi = 0; mi < 4; mi++) {
#pragma unroll
        for (int ni = 0; ni < 4; ni++) {
            int r0 = cRow * 128 + wm * 64 + mi * 16 + quad;
            int c0 = cCol * 128 + wn * 32 + ni * 8 + 2 * qt;
            float b0 = bias ? bias[c0] : 0.f;
            float b1 = bias ? bias[c0 + 1] : 0.f;
            float2 v01 = make_float2(acc[mi][ni][0] + b0, acc[mi][ni][1] + b1);
            float2 v23 = make_float2(acc[mi][ni][2] + b0, acc[mi][ni][3] + b1);
            *(float2*)&C[(size_t)r0 * N + c0] = v01;
            *(float2*)&C[(size_t)(r0 + 8) * N + c0] = v23;
        }
    }
}

// ---------------- K2: orientation bins (no S write; packed polar) ---------
// grid (XL/512, H, B), block 128 (thread = k)
__global__ __launch_bounds__(128) void k2_scores()
{
    int k = threadIdx.x;
    int xc = blockIdx.x, h = blockIdx.y, b = blockIdx.z;
    int bh = b * H_ + h;
    int xbase = xc * 512;
    __shared__ float kx_sh[64 * 32];
    __shared__ unsigned pk_sh[128 * 33];    // u16[128][66] as u32[128][33]

    float4 kq4[8];
    const float4* kqp = (const float4*)&g_QKVk[((size_t)(b * KL + k)) * TDIM + h * HD];
#pragma unroll
    for (int i = 0; i < 8; i++) kq4[i] = kqp[i];

    float bins[8];
#pragma unroll
    for (int o = 0; o < 8; o++) bins[o] = 0.f;

    const unsigned* pkg = (const unsigned*)&g_pack[(size_t)bh * KL * XL];

    for (int c = 0; c < 8; c++) {
        int xs = xbase + c * 64;
        __syncthreads();
        for (int g = threadIdx.x; g < 512; g += 128) {
            int row = g >> 3, c4 = g & 7;
            ((float4*)kx_sh)[g] =
                *(const float4*)&g_QKVx[((size_t)(b * XL + xs + row)) * TDIM + DIM + h * HD + c4 * 4];
        }
        for (int g = threadIdx.x; g < 128 * 32; g += 128) {
            int row = g >> 5, col = g & 31;
            pk_sh[row * 33 + col] = pkg[(size_t)row * (XL / 2) + (xs >> 1) + col];
        }
        __syncthreads();
        const unsigned short* prow = (const unsigned short*)&pk_sh[k * 33];
        for (int j0 = 0; j0 < 64; j0 += 4) {
#pragma unroll
            for (int jj = 0; jj < 4; jj++) {
                const float4* kx4 = (const float4*)&kx_sh[(j0 + jj) * 32];
                float a = 0.f;
#pragma unroll
                for (int d = 0; d < 8; d++) {
                    float4 v = kx4[d];
                    a += v.x * kq4[d].x + v.y * kq4[d].y + v.z * kq4[d].z + v.w * kq4[d].w;
                }
                float as = fabsf(a * SCALE);
                int pv = (prow[j0 + jj] >> 7) & 7;
#pragma unroll
                for (int o = 0; o < 8; o++) bins[o] += (pv == o) ? as : 0.f;
            }
        }
    }
    float* orow = &g_oriP[((size_t)xc * B_ * H_ * KL + bh * KL + k) * 8];
#pragma unroll
    for (int o = 0; o < 8; o++) orow[o] = bins[o];
}

// ---------------- K2c: reduce slices + argmax ----------------
__global__ void k2_argmax()
{
    int idx = blockIdx.x * blockDim.x + threadIdx.x;
    if (idx >= B_ * H_ * KL) return;
    float s[8];
#pragma unroll
    for (int o = 0; o < 8; o++) s[o] = 0.f;
#pragma unroll
    for (int xc = 0; xc < 8; xc++) {
        const float* p = &g_oriP[((size_t)xc * B_ * H_ * KL + idx) * 8];
#pragma unroll
        for (int o = 0; o < 8; o++) s[o] += p[o];
    }
    int best = 0;
    float bv = s[0];
#pragma unroll
    for (int p = 1; p < 8; p++)
        if (s[p] > bv) { bv = s[p]; best = p; }
    g_mo[idx] = best;
}

// ---------------- K3: kernel->x attention (recompute scores, packed) ------
// grid (8 x-splits, H, B), block 128 (thread = k)
__global__ __launch_bounds__(128) void k3_kattn(
    const float* __restrict__ dis_embed, const float* __restrict__ polar_emb)
{
    int k = threadIdx.x;
    int xs = blockIdx.x, h = blockIdx.y, b = blockIdx.z;
    int bh = b * H_ + h;
    __shared__ float kx_sh[64 * 32];
    __shared__ float V_sh[64 * 32];
    __shared__ unsigned pk_sh[128 * 33];
    __shared__ float de_sh[NDIS];
    __shared__ float pe_sh[8];
    if (k < NDIS) de_sh[k] = dis_embed[k * H_ + h];
    if (k < 8) pe_sh[k] = polar_emb[k];
    int mo = g_mo[bh * KL + k];

    float4 kq4[8];
    const float4* kqp = (const float4*)&g_QKVk[((size_t)(b * KL + k)) * TDIM + h * HD];
#pragma unroll
    for (int i = 0; i < 8; i++) kq4[i] = kqp[i];

    const unsigned* pkg = (const unsigned*)&g_pack[(size_t)bh * KL * XL];

    float m = -1e30f, l = 0.f;
    float acc[32];
#pragma unroll
    for (int d = 0; d < 32; d++) acc[d] = 0.f;

    int xbase = xs * 512;
    for (int c = 0; c < 8; c++) {
        int x0 = xbase + c * 64;
        __syncthreads();
        for (int g = threadIdx.x; g < 512; g += 128) {
            int row = g >> 3, c4 = g & 7;
            size_t rb = ((size_t)(b * XL + x0 + row)) * TDIM + h * HD + c4 * 4;
            ((float4*)kx_sh)[g] = *(const float4*)&g_QKVx[rb + DIM];
            ((float4*)V_sh)[g]  = *(const float4*)&g_QKVx[rb + 2 * DIM];
        }
        for (int g = threadIdx.x; g < 128 * 32; g += 128) {
            int row = g >> 5, col = g & 31;
            pk_sh[row * 33 + col] = pkg[(size_t)row * (XL / 2) + (x0 >> 1) + col];
        }
        __syncthreads();
        const unsigned short* prow = (const unsigned short*)&pk_sh[k * 33];
        for (int j0 = 0; j0 < 64; j0 += 4) {
#pragma unroll
            for (int jj = 0; jj < 4; jj++) {
                int j = j0 + jj;
                const float4* kx4 = (const float4*)&kx_sh[j * 32];
                float a = 0.f;
#pragma unroll
                for (int d = 0; d < 8; d++) {
                    float4 v = kx4[d];
                    a += v.x * kq4[d].x + v.y * kq4[d].y + v.z * kq4[d].z + v.w * kq4[d].w;
                }
                float s = a * SCALE;
                unsigned short p = prow[j];
                int rv = p & 127;
                int pv = (p >> 7) & 7;
                float t = ((p >> 10) ? -1e6f : s) + de_sh[rv] + pe_sh[(pv - mo) & 7];
                float mn = fmaxf(m, t);
                float eo = __expf(m - mn);
                float w  = __expf(t - mn);
                l = l * eo + w;
                m = mn;
                const float4* vp = (const float4*)&V_sh[j * 32];
#pragma unroll
                for (int d = 0; d < 8; d++) {
                    float4 v = vp[d];
                    acc[d * 4 + 0] = acc[d * 4 + 0] * eo + w * v.x;
                    acc[d * 4 + 1] = acc[d * 4 + 1] * eo + w * v.y;
                    acc[d * 4 + 2] = acc[d * 4 + 2] * eo + w * v.z;
                    acc[d * 4 + 3] = acc[d * 4 + 3] * eo + w * v.w;
                }
            }
        }
    }
    float* pp = &g_part[(((size_t)bh * 8 + xs) * KL + k) * 34];
    pp[0] = m;
    pp[1] = l;
#pragma unroll
    for (int d = 0; d < 32; d++) pp[2 + d] = acc[d];
}

// ---------------- K3c: combine x-splits -> preK ----------------
__global__ void k3_combine()
{
    int idx = blockIdx.x * blockDim.x + threadIdx.x;
    if (idx >= B_ * H_ * KL) return;
    int k = idx % KL, bh = idx / KL;
    int h = bh % H_, b = bh / H_;
    const int SSTR = KL * 34;
    const float* base = &g_part[((size_t)bh * 8) * SSTR + k * 34];
    float M = -1e30f;
#pragma unroll
    for (int s = 0; s < 8; s++) M = fmaxf(M, base[s * SSTR]);
    float es[8], L = 0.f;
#pragma unroll
    for (int s = 0; s < 8; s++) {
        es[s] = __expf(base[s * SSTR] - M);
        L += base[s * SSTR + 1] * es[s];
    }
    float invL = 1.f / L;
    float* out = &g_preK[((size_t)b * KL + k) * DIM + h * HD];
#pragma unroll
    for (int d = 0; d < 32; d++) {
        float a = 0.f;
#pragma unroll
        for (int s = 0; s < 8; s++) a += base[s * SSTR + 2 + d] * es[s];
        out[d] = a * invL;
    }
}

// ---------------- K4: x->kernel attention (packed bias reads) -------------
// grid (XL/256, H, B), block 256 (thread = x)
__global__ __launch_bounds__(256) void k4_xattn(
    const float* __restrict__ dis_embed, const float* __restrict__ polar_emb)
{
    __shared__ float kk_sh[KL * HD];
    __shared__ float kv_sh[KL * HD];
    __shared__ float de_sh[NDIS];
    __shared__ float pe_sh[8];
    __shared__ int   mo_sh[KL];
    int tid = threadIdx.x;
    int xc = blockIdx.x, h = blockIdx.y, b = blockIdx.z;
    int bh = b * H_ + h;

    for (int g = tid; g < KL * HD / 4; g += 256) {
        int row = g >> 3, c4 = g & 7;
        ((float4*)kk_sh)[g] =
            *(const float4*)&g_QKVk[((size_t)(b * KL + row)) * TDIM + DIM + h * HD + c4 * 4];
        ((float4*)kv_sh)[g] =
            *(const float4*)&g_QKVk[((size_t)(b * KL + row)) * TDIM + 2 * DIM + h * HD + c4 * 4];
    }
    if (tid < NDIS) de_sh[tid] = dis_embed[tid * H_ + h];
    if (tid < 8) pe_sh[tid] = polar_emb[tid];
    if (tid < KL) mo_sh[tid] = g_mo[bh * KL + tid];
    __syncthreads();

    int x = xc * 256 + tid;
    float4 q4[8];
    const float4* qp = (const float4*)&g_QKVx[((size_t)(b * XL + x)) * TDIM + h * HD];
#pragma unroll
    for (int i = 0; i < 8; i++) q4[i] = qp[i];
    const unsigned short* pk = &g_pack[(size_t)bh * KL * XL + x];

    float m = -1e30f, l = 0.f;
    float acc[32];
#pragma unroll
    for (int d = 0; d < 32; d++) acc[d] = 0.f;

    for (int k0 = 0; k0 < KL; k0 += 4) {
#pragma unroll
        for (int ki = 0; ki < 4; ki++) {
            int kidx = k0 + ki;
            const float4* kkp = (const float4*)&kk_sh[kidx * HD];
            float s = 0.f;
#pragma unroll
            for (int d = 0; d < 8; d++) {
                float4 a = kkp[d];
                s += a.x * q4[d].x + a.y * q4[d].y + a.z * q4[d].z + a.w * q4[d].w;
            }
            s *= SCALE;
            unsigned short p = pk[(size_t)kidx * XL];
            int rv = p & 127;
            int pv = (p >> 7) & 7;
            float t = ((p >> 10) ? -1e9f : s) + de_sh[rv] + pe_sh[(pv - mo_sh[kidx]) & 7];
            float mn = fmaxf(m, t);
            float eo = __expf(m - mn);
            float w  = __expf(t - mn);
            l = l * eo + w;
            m = mn;
            const float4* vp = (const float4*)&kv_sh[kidx * HD];
#pragma unroll
            for (int d = 0; d < 8; d++) {
                float4 v = vp[d];
                acc[d * 4 + 0] = acc[d * 4 + 0] * eo + w * v.x;
                acc[d * 4 + 1] = acc[d * 4 + 1] * eo + w * v.y;
                acc[d * 4 + 2] = acc[d * 4 + 2] * eo + w * v.z;
                acc[d * 4 + 3] = acc[d * 4 + 3] * eo + w * v.w;
            }
        }
    }
    float invl = 1.f / l;
    float* out = &g_preX[((size_t)(b * XL + x)) * DIM + h * HD];
#pragma unroll
    for (int d = 0; d < 8; d++) {
        float4 v;
        v.x = acc[d * 4 + 0] * invl;
        v.y = acc[d * 4 + 1] * invl;
        v.z = acc[d * 4 + 2] * invl;
        v.w = acc[d * 4 + 3] * invl;
        *(float4*)&out[d * 4] = v;
    }
}

// ---------------- host launcher ----------------
extern "C" void kernel_launch(void* const* d_in, const int* in_sizes, int n_in,
                              void* d_out, int out_size)
{
    const float* x     = (const float*)d_in[0];
    const float* kern  = (const float*)d_in[1];
    const int*   rd    = (const int*)d_in[2];
    const int*   polar = (const int*)d_in[3];
    const void*  mask  = d_in[4];
    const float* Wqkv  = (const float*)d_in[5];
    const float* dis   = (const float*)d_in[6];
    const float* pemb  = (const float*)d_in[7];
    const float* Wproj = (const float*)d_in[8];
    const float* bproj = (const float*)d_in[9];
    float* out = (float*)d_out;

    float* pQKVx; cudaGetSymbolAddress((void**)&pQKVx, g_QKVx);
    float* pQKVk; cudaGetSymbolAddress((void**)&pQKVk, g_QKVk);
    float* pPreX; cudaGetSymbolAddress((void**)&pPreX, g_preX);
    float* pPreK; cudaGetSymbolAddress((void**)&pPreK, g_preK);

    // mask dtype probe + packed bias table
    det_reset<<<1, 32>>>();
    det_scan<<<4096, 256>>>((const unsigned*)mask);
    pack16<<<dim3(XL / 64, KL / 32, B_), dim3(32, 8)>>>(mask, rd, polar);

    // QKV projections (3xTF32 tensor cores)
    gemm_tf32<<<dim3(TDIM / 128, (B_ * XL) / 128), 256>>>(x, Wqkv, nullptr, pQKVx, B_ * XL, TDIM, DIM);
    gemm_tf32<<<dim3(TDIM / 128, (B_ * KL) / 128), 256>>>(kern, Wqkv, nullptr, pQKVk, B_ * KL, TDIM, DIM);

    // orientation bins + argmax
    k2_scores<<<dim3(XL / 512, H_, B_), 128>>>();
    k2_argmax<<<(B_ * H_ * KL + 255) / 256, 256>>>();

    // kernel->x attention
    k3_kattn<<<dim3(8, H_, B_), 128>>>(dis, pemb);
    k3_combine<<<(B_ * H_ * KL + 255) / 256, 256>>>();

    // x->kernel attention
    k4_xattn<<<dim3(XL / 256, H_, B_), 256>>>(dis, pemb);

    // output projections
    gemm_tf32<<<dim3(DIM / 128, (B_ * XL) / 128), 256>>>(pPreX, Wproj, bproj, out, B_ * XL, DIM, DIM);
    gemm_tf32<<<dim3(DIM / 128, (B_ * KL) / 128), 256>>>(pPreK, Wproj, bproj, out + (size_t)B_ * XL * DIM, B_ * KL, DIM, DIM);
}

// round 7
// speedup vs baseline: 2.0463x; 1.1952x over previous
#include <cuda_runtime.h>
#include <cstdint>

#define B_    4
#define KL    128
#define XL    4096
#define DIM   256
#define H_    8
#define HD    32
#define PB    8
#define NDIS  66
#define TDIM  768           // 3*DIM
#define SCALE 0.17677669529663687f
#define NMASK (B_ * H_ * XL * KL)
#define NSPLIT 32           // x-splits for k2/k3

// ---------------- scratch (device globals) ----------------
__device__ float    g_QKVx[B_ * XL * TDIM];
__device__ float    g_QKVk[B_ * KL * TDIM];
__device__ unsigned short g_pack[(size_t)NMASK];       // (b,h,k,x): rd | polar<<7 | mask<<10
__device__ float    g_oriP[NSPLIT * B_ * H_ * KL * PB];
__device__ int      g_mo[B_ * H_ * KL];
__device__ float    g_part[(size_t)B_ * H_ * NSPLIT * KL * 33];  // (l, acc[32])
__device__ float    g_preK[B_ * KL * DIM];
__device__ float    g_preX[B_ * XL * DIM];
__device__ unsigned g_flags;

// ---------------- mask dtype probe ----------------
__global__ void det_reset() { if (threadIdx.x == 0) g_flags = 0u; }

__global__ void det_scan(const unsigned* __restrict__ w)
{
    int i = blockIdx.x * blockDim.x + threadIdx.x;
    unsigned v = w[i];
    unsigned f = 0;
    if (v == 0x3F800000u) f |= 1u;
    else if (v != 0u && v != 1u) f |= 2u;
    for (int o = 16; o > 0; o >>= 1) f |= __shfl_xor_sync(0xffffffffu, f, o);
    if ((threadIdx.x & 31) == 0 && f) atomicOr(&g_flags, f);
}

// ---------------- pack16: rd+polar+mask(transposed) -> u16 (b,h,k,x) ------
__global__ void pack16(const void* __restrict__ mask,
                       const int* __restrict__ rd, const int* __restrict__ polar)
{
    __shared__ unsigned short rp_sh[32][66];
    __shared__ uint8_t m_sh[64][36];
    unsigned flags = g_flags;
    int mode = (flags & 1u) ? 2 : ((flags & 2u) ? 0 : 1);
    int x0 = blockIdx.x * 64, k0 = blockIdx.y * 32, b = blockIdx.z;
    int tx = threadIdx.x, ty = threadIdx.y;

#pragma unroll
    for (int ki = ty; ki < 32; ki += 8) {
        size_t rowb = ((size_t)(b * KL + k0 + ki)) * XL + x0;
#pragma unroll
        for (int xx = tx; xx < 64; xx += 32) {
            int r = rd[rowb + xx];
            int p = polar[rowb + xx];
            rp_sh[ki][xx] = (unsigned short)(r | (p << 7));
        }
    }
    for (int h = 0; h < H_; h++) {
        size_t mb = ((size_t)((b * H_ + h)) * XL + x0) * KL + k0;
#pragma unroll
        for (int xi = ty; xi < 64; xi += 8) {
            uint8_t v;
            if (mode == 1)      v = ((const int*)mask)[mb + (size_t)xi * KL + tx] != 0;
            else if (mode == 2) v = ((const float*)mask)[mb + (size_t)xi * KL + tx] != 0.f;
            else                v = ((const uint8_t*)mask)[mb + (size_t)xi * KL + tx] != 0;
            m_sh[xi][tx] = v;
        }
        __syncthreads();
        size_t ob = ((size_t)((b * H_ + h) * KL + k0)) * XL + x0;
#pragma unroll
        for (int ki = ty; ki < 32; ki += 8)
#pragma unroll
            for (int xx = tx; xx < 64; xx += 32)
                g_pack[ob + (size_t)ki * XL + xx] =
                    (unsigned short)(rp_sh[ki][xx] | ((unsigned short)m_sh[xx][ki] << 10));
        __syncthreads();
    }
}

// ---------------- 3xTF32 tensor-core GEMM (proven) -------------
__device__ __forceinline__ void split_tf32(float x, uint32_t& hi, uint32_t& lo)
{
    asm("cvt.rna.tf32.f32 %0, %1;" : "=r"(hi) : "f"(x));
    float r = x - __uint_as_float(hi);
    asm("cvt.rna.tf32.f32 %0, %1;" : "=r"(lo) : "f"(r));
}

__device__ __forceinline__ void mma_tf32(float* c, const uint32_t* a, uint32_t b0, uint32_t b1)
{
    asm("mma.sync.aligned.m16n8k8.row.col.f32.tf32.tf32.f32 "
        "{%0,%1,%2,%3}, {%4,%5,%6,%7}, {%8,%9}, {%0,%1,%2,%3};"
        : "+f"(c[0]), "+f"(c[1]), "+f"(c[2]), "+f"(c[3])
        : "r"(a[0]), "r"(a[1]), "r"(a[2]), "r"(a[3]), "r"(b0), "r"(b1));
}

__global__ __launch_bounds__(256, 2) void gemm_tf32(
    const float* __restrict__ A, const float* __restrict__ Bm,
    const float* __restrict__ bias, float* __restrict__ C,
    int M, int N, int K)
{
    __shared__ float As[128][36];
    __shared__ float Bs[32][132];
    int tid = threadIdx.x;
    int wid = tid >> 5, lane = tid & 31;
    int quad = lane >> 2, qt = lane & 3;
    int wm = wid & 1, wn = wid >> 1;
    int cCol = blockIdx.x, cRow = blockIdx.y;
    const float* Ap = A + (size_t)cRow * 128 * K;
    const float* Bp = Bm + cCol * 128;

    float acc[4][4][4];
#pragma unroll
    for (int i = 0; i < 4; i++)
#pragma unroll
        for (int j = 0; j < 4; j++)
#pragma unroll
            for (int c = 0; c < 4; c++) acc[i][j][c] = 0.f;

    for (int k0 = 0; k0 < K; k0 += 32) {
#pragma unroll
        for (int j = 0; j < 4; j++) {
            int f = tid + 256 * j;
            int r = f >> 3, s = f & 7;
            float4 v = *(const float4*)&Ap[(size_t)r * K + k0 + s * 4];
            *(float4*)&As[r][s * 4] = v;
        }
#pragma unroll
        for (int j = 0; j < 4; j++) {
            int f = tid + 256 * j;
            int r = f >> 5, s = f & 31;
            float4 v = *(const float4*)&Bp[(size_t)(k0 + r) * N + s * 4];
            *(float4*)&Bs[r][s * 4] = v;
        }
        __syncthreads();

#pragma unroll
        for (int kk = 0; kk < 4; kk++) {
            uint32_t ahi[4][4], alo[4][4];
#pragma unroll
            for (int mi = 0; mi < 4; mi++) {
                int ar = wm * 64 + mi * 16 + quad;
                int ac = kk * 8 + qt;
                split_tf32(As[ar][ac],          ahi[mi][0], alo[mi][0]);
                split_tf32(As[ar + 8][ac],      ahi[mi][1], alo[mi][1]);
                split_tf32(As[ar][ac + 4],      ahi[mi][2], alo[mi][2]);
                split_tf32(As[ar + 8][ac + 4],  ahi[mi][3], alo[mi][3]);
            }
#pragma unroll
            for (int ni = 0; ni < 4; ni++) {
                int bc = wn * 32 + ni * 8 + quad;
                int br = kk * 8 + qt;
                uint32_t bh0, bh1, bl0, bl1;
                split_tf32(Bs[br][bc],     bh0, bl0);
                split_tf32(Bs[br + 4][bc], bh1, bl1);
#pragma unroll
                for (int mi = 0; mi < 4; mi++) {
                    mma_tf32(acc[mi][ni], ahi[mi], bh0, bh1);
                    mma_tf32(acc[mi][ni], alo[mi], bh0, bh1);
                    mma_tf32(acc[mi][ni], ahi[mi], bl0, bl1);
                }
            }
        }
        __syncthreads();
    }

#pragma unroll
    for (int mi = 0; mi < 4; mi++) {
#pragma unroll
        for (int ni = 0; ni < 4; ni++) {
            int r0 = cRow * 128 + wm * 64 + mi * 16 + quad;
            int c0 = cCol * 128 + wn * 32 + ni * 8 + 2 * qt;
            float b0 = bias ? bias[c0] : 0.f;
            float b1 = bias ? bias[c0 + 1] : 0.f;
            float2 v01 = make_float2(acc[mi][ni][0] + b0, acc[mi][ni][1] + b1);
            float2 v23 = make_float2(acc[mi][ni][2] + b0, acc[mi][ni][3] + b1);
            *(float2*)&C[(size_t)r0 * N + c0] = v01;
            *(float2*)&C[(size_t)(r0 + 8) * N + c0] = v23;
        }
    }
}

// ---------------- K2: orientation bins ----------------
// grid (NSPLIT, H, B), block 128 (thread = k); 128 x per block
__global__ __launch_bounds__(128) void k2_scores()
{
    int k = threadIdx.x;
    int xc = blockIdx.x, h = blockIdx.y, b = blockIdx.z;
    int bh = b * H_ + h;
    int xbase = xc * (XL / NSPLIT);
    __shared__ float kx_sh[64 * 32];
    __shared__ unsigned pk_sh[128 * 33];

    float4 kq4[8];
    const float4* kqp = (const float4*)&g_QKVk[((size_t)(b * KL + k)) * TDIM + h * HD];
#pragma unroll
    for (int i = 0; i < 8; i++) kq4[i] = kqp[i];

    float bins[8];
#pragma unroll
    for (int o = 0; o < 8; o++) bins[o] = 0.f;

    const unsigned* pkg = (const unsigned*)&g_pack[(size_t)bh * KL * XL];

    for (int c = 0; c < 2; c++) {
        int xs = xbase + c * 64;
        __syncthreads();
        for (int g = threadIdx.x; g < 512; g += 128) {
            int row = g >> 3, c4 = g & 7;
            ((float4*)kx_sh)[g] =
                *(const float4*)&g_QKVx[((size_t)(b * XL + xs + row)) * TDIM + DIM + h * HD + c4 * 4];
        }
        for (int g = threadIdx.x; g < 128 * 32; g += 128) {
            int row = g >> 5, col = g & 31;
            pk_sh[row * 33 + col] = pkg[(size_t)row * (XL / 2) + (xs >> 1) + col];
        }
        __syncthreads();
        const unsigned short* prow = (const unsigned short*)&pk_sh[k * 33];
        for (int j0 = 0; j0 < 64; j0 += 4) {
#pragma unroll
            for (int jj = 0; jj < 4; jj++) {
                const float4* kx4 = (const float4*)&kx_sh[(j0 + jj) * 32];
                float a = 0.f;
#pragma unroll
                for (int d = 0; d < 8; d++) {
                    float4 v = kx4[d];
                    a += v.x * kq4[d].x + v.y * kq4[d].y + v.z * kq4[d].z + v.w * kq4[d].w;
                }
                float as = fabsf(a * SCALE);
                int pv = (prow[j0 + jj] >> 7) & 7;
#pragma unroll
                for (int o = 0; o < 8; o++) bins[o] += (pv == o) ? as : 0.f;
            }
        }
    }
    float* orow = &g_oriP[((size_t)xc * B_ * H_ * KL + bh * KL + k) * 8];
#pragma unroll
    for (int o = 0; o < 8; o++) orow[o] = bins[o];
}

// ---------------- K2c: reduce slices + argmax ----------------
__global__ void k2_argmax()
{
    int idx = blockIdx.x * blockDim.x + threadIdx.x;
    if (idx >= B_ * H_ * KL) return;
    float s[8];
#pragma unroll
    for (int o = 0; o < 8; o++) s[o] = 0.f;
    for (int xc = 0; xc < NSPLIT; xc++) {
        const float* p = &g_oriP[((size_t)xc * B_ * H_ * KL + idx) * 8];
#pragma unroll
        for (int o = 0; o < 8; o++) s[o] += p[o];
    }
    int best = 0;
    float bv = s[0];
#pragma unroll
    for (int p = 1; p < 8; p++)
        if (s[p] > bv) { bv = s[p]; best = p; }
    g_mo[idx] = best;
}

// ---------------- K3: kernel->x attention (no-max softmax, 32 splits) -----
// grid (NSPLIT, H, B), block 128 (thread = k)
__global__ __launch_bounds__(128) void k3_kattn(
    const float* __restrict__ dis_embed, const float* __restrict__ polar_emb)
{
    int k = threadIdx.x;
    int xs = blockIdx.x, h = blockIdx.y, b = blockIdx.z;
    int bh = b * H_ + h;
    __shared__ float kx_sh[64 * 32];
    __shared__ float V_sh[64 * 32];
    __shared__ unsigned pk_sh[128 * 33];
    __shared__ float de_sh[NDIS];
    __shared__ float pe_sh[8];
    if (k < NDIS) de_sh[k] = dis_embed[k * H_ + h];
    if (k < 8) pe_sh[k] = polar_emb[k];
    int mo = g_mo[bh * KL + k];

    float4 kq4[8];
    const float4* kqp = (const float4*)&g_QKVk[((size_t)(b * KL + k)) * TDIM + h * HD];
#pragma unroll
    for (int i = 0; i < 8; i++) kq4[i] = kqp[i];

    const unsigned* pkg = (const unsigned*)&g_pack[(size_t)bh * KL * XL];

    float l = 0.f;
    float acc[32];
#pragma unroll
    for (int d = 0; d < 32; d++) acc[d] = 0.f;

    int xbase = xs * (XL / NSPLIT);
    for (int c = 0; c < 2; c++) {
        int x0 = xbase + c * 64;
        __syncthreads();
        for (int g = threadIdx.x; g < 512; g += 128) {
            int row = g >> 3, c4 = g & 7;
            size_t rb = ((size_t)(b * XL + x0 + row)) * TDIM + h * HD + c4 * 4;
            ((float4*)kx_sh)[g] = *(const float4*)&g_QKVx[rb + DIM];
            ((float4*)V_sh)[g]  = *(const float4*)&g_QKVx[rb + 2 * DIM];
        }
        for (int g = threadIdx.x; g < 128 * 32; g += 128) {
            int row = g >> 5, col = g & 31;
            pk_sh[row * 33 + col] = pkg[(size_t)row * (XL / 2) + (x0 >> 1) + col];
        }
        __syncthreads();
        const unsigned short* prow = (const unsigned short*)&pk_sh[k * 33];
        for (int j0 = 0; j0 < 64; j0 += 4) {
#pragma unroll
            for (int jj = 0; jj < 4; jj++) {
                int j = j0 + jj;
                const float4* kx4 = (const float4*)&kx_sh[j * 32];
                float a = 0.f;
#pragma unroll
                for (int d = 0; d < 8; d++) {
                    float4 v = kx4[d];
                    a += v.x * kq4[d].x + v.y * kq4[d].y + v.z * kq4[d].z + v.w * kq4[d].w;
                }
                unsigned short p = prow[j];
                float t = a * SCALE + de_sh[p & 127] + pe_sh[(((p >> 7) & 7) - mo) & 7];
                float w = (p >> 10) ? 0.f : __expf(t);
                l += w;
                const float4* vp = (const float4*)&V_sh[j * 32];
#pragma unroll
                for (int d = 0; d < 8; d++) {
                    float4 v = vp[d];
                    acc[d * 4 + 0] += w * v.x;
                    acc[d * 4 + 1] += w * v.y;
                    acc[d * 4 + 2] += w * v.z;
                    acc[d * 4 + 3] += w * v.w;
                }
            }
        }
    }
    float* pp = &g_part[(((size_t)bh * NSPLIT + xs) * KL + k) * 33];
    pp[0] = l;
#pragma unroll
    for (int d = 0; d < 32; d++) pp[1 + d] = acc[d];
}

// ---------------- K3c: combine x-splits -> preK ----------------
// thread = (bh, k, d); 131072 threads
__global__ void k3_combine()
{
    int idx = blockIdx.x * blockDim.x + threadIdx.x;
    if (idx >= B_ * H_ * KL * 32) return;
    int d = idx & 31;
    int k = (idx >> 5) & (KL - 1);
    int bh = idx >> 12;
    int h = bh % H_, b = bh / H_;
    const float* base = &g_part[((size_t)bh * NSPLIT) * KL * 33 + (size_t)k * 33];
    float L = 0.f, A = 0.f;
    const size_t SSTR = (size_t)KL * 33;
#pragma unroll 8
    for (int s = 0; s < NSPLIT; s++) {
        L += base[s * SSTR];
        A += base[s * SSTR + 1 + d];
    }
    g_preK[((size_t)b * KL + k) * DIM + h * HD + d] = A / L;
}

// ---------------- K4: x->kernel attention (no-max softmax) ----------------
// grid (XL/128, H, B), block 128 (thread = x)
__global__ __launch_bounds__(128) void k4_xattn(
    const float* __restrict__ dis_embed, const float* __restrict__ polar_emb)
{
    __shared__ float kk_sh[KL * HD];
    __shared__ float kv_sh[KL * HD];
    __shared__ float de_sh[NDIS];
    __shared__ float pe_sh[8];
    __shared__ int   mo_sh[KL];
    int tid = threadIdx.x;
    int xc = blockIdx.x, h = blockIdx.y, b = blockIdx.z;
    int bh = b * H_ + h;

    for (int g = tid; g < KL * HD / 4; g += 128) {
        int row = g >> 3, c4 = g & 7;
        ((float4*)kk_sh)[g] =
            *(const float4*)&g_QKVk[((size_t)(b * KL + row)) * TDIM + DIM + h * HD + c4 * 4];
        ((float4*)kv_sh)[g] =
            *(const float4*)&g_QKVk[((size_t)(b * KL + row)) * TDIM + 2 * DIM + h * HD + c4 * 4];
    }
    if (tid < NDIS) de_sh[tid] = dis_embed[tid * H_ + h];
    if (tid < 8) pe_sh[tid] = polar_emb[tid];
    if (tid < KL) mo_sh[tid] = g_mo[bh * KL + tid];
    __syncthreads();

    int x = xc * 128 + tid;
    float4 q4[8];
    const float4* qp = (const float4*)&g_QKVx[((size_t)(b * XL + x)) * TDIM + h * HD];
#pragma unroll
    for (int i = 0; i < 8; i++) q4[i] = qp[i];
    const unsigned short* pk = &g_pack[(size_t)bh * KL * XL + x];

    float l = 0.f;
    float acc[32];
#pragma unroll
    for (int d = 0; d < 32; d++) acc[d] = 0.f;

    for (int k0 = 0; k0 < KL; k0 += 4) {
#pragma unroll
        for (int ki = 0; ki < 4; ki++) {
            int kidx = k0 + ki;
            const float4* kkp = (const float4*)&kk_sh[kidx * HD];
            float s = 0.f;
#pragma unroll
            for (int d = 0; d < 8; d++) {
                float4 a = kkp[d];
                s += a.x * q4[d].x + a.y * q4[d].y + a.z * q4[d].z + a.w * q4[d].w;
            }
            unsigned short p = pk[(size_t)kidx * XL];
            float t = s * SCALE + de_sh[p & 127] + pe_sh[(((p >> 7) & 7) - mo_sh[kidx]) & 7];
            float w = (p >> 10) ? 0.f : __expf(t);
            l += w;
            const float4* vp = (const float4*)&kv_sh[kidx * HD];
#pragma unroll
            for (int d = 0; d < 8; d++) {
                float4 v = vp[d];
                acc[d * 4 + 0] += w * v.x;
                acc[d * 4 + 1] += w * v.y;
                acc[d * 4 + 2] += w * v.z;
                acc[d * 4 + 3] += w * v.w;
            }
        }
    }
    float invl = 1.f / l;
    float* out = &g_preX[((size_t)(b * XL + x)) * DIM + h * HD];
#pragma unroll
    for (int d = 0; d < 8; d++) {
        float4 v;
        v.x = acc[d * 4 + 0] * invl;
        v.y = acc[d * 4 + 1] * invl;
        v.z = acc[d * 4 + 2] * invl;
        v.w = acc[d * 4 + 3] * invl;
        *(float4*)&out[d * 4] = v;
    }
}

// ---------------- host launcher ----------------
extern "C" void kernel_launch(void* const* d_in, const int* in_sizes, int n_in,
                              void* d_out, int out_size)
{
    const float* x     = (const float*)d_in[0];
    const float* kern  = (const float*)d_in[1];
    const int*   rd    = (const int*)d_in[2];
    const int*   polar = (const int*)d_in[3];
    const void*  mask  = d_in[4];
    const float* Wqkv  = (const float*)d_in[5];
    const float* dis   = (const float*)d_in[6];
    const float* pemb  = (const float*)d_in[7];
    const float* Wproj = (const float*)d_in[8];
    const float* bproj = (const float*)d_in[9];
    float* out = (float*)d_out;

    float* pQKVx; cudaGetSymbolAddress((void**)&pQKVx, g_QKVx);
    float* pQKVk; cudaGetSymbolAddress((void**)&pQKVk, g_QKVk);
    float* pPreX; cudaGetSymbolAddress((void**)&pPreX, g_preX);
    float* pPreK; cudaGetSymbolAddress((void**)&pPreK, g_preK);

    // mask dtype probe + packed bias table
    det_reset<<<1, 32>>>();
    det_scan<<<4096, 256>>>((const unsigned*)mask);
    pack16<<<dim3(XL / 64, KL / 32, B_), dim3(32, 8)>>>(mask, rd, polar);

    // QKV projections (3xTF32 tensor cores)
    gemm_tf32<<<dim3(TDIM / 128, (B_ * XL) / 128), 256>>>(x, Wqkv, nullptr, pQKVx, B_ * XL, TDIM, DIM);
    gemm_tf32<<<dim3(TDIM / 128, (B_ * KL) / 128), 256>>>(kern, Wqkv, nullptr, pQKVk, B_ * KL, TDIM, DIM);

    // orientation bins + argmax
    k2_scores<<<dim3(NSPLIT, H_, B_), 128>>>();
    k2_argmax<<<(B_ * H_ * KL + 255) / 256, 256>>>();

    // kernel->x attention
    k3_kattn<<<dim3(NSPLIT, H_, B_), 128>>>(dis, pemb);
    k3_combine<<<(B_ * H_ * KL * 32 + 255) / 256, 256>>>();

    // x->kernel attention
    k4_xattn<<<dim3(XL / 128, H_, B_), 128>>>(dis, pemb);

    // output projections
    gemm_tf32<<<dim3(DIM / 128, (B_ * XL) / 128), 256>>>(pPreX, Wproj, bproj, out, B_ * XL, DIM, DIM);
    gemm_tf32<<<dim3(DIM / 128, (B_ * KL) / 128), 256>>>(pPreK, Wproj, bproj, out + (size_t)B_ * XL * DIM, B_ * KL, DIM, DIM);
}